// round 15
// baseline (speedup 1.0000x reference)
#include <cuda_runtime.h>
#include <cuda_bf16.h>
#include <cuda_fp16.h>
#include <cstdint>

#define DIMN 128
#define NMAX 100000
#define EMAX 600000

// ---------------- scratch (device globals; no allocation allowed) -------------
__device__ __half   g_q[NMAX * DIMN];     // fp16 projections
__device__ __half   g_k[NMAX * DIMN];
__device__ __half   g_u[NMAX * DIMN];     // u = h @ (Wp@Wv)^T
__device__ float    g_agg[NMAX * DIMN];   // fp32 accumulator
__device__ float    g_sum[NMAX];
__device__ int      g_cnt[NMAX];
__device__ int      g_pos[NMAX];
__device__ int      g_blk[128];
__device__ int      g_blkoff[128];
__device__ int2     g_e2[EMAX];           // dst-sorted edges: (src, dst)
__device__ float    g_wpv[DIMN * DIMN];   // P = Wp @ Wv (fp32)
__device__ __half   g_wf[3 * DIMN * DIMN];  // fp16 Wq, Wk, P

// ---------------- smem layout (bytes, dynamic) ---------------------------------
// 64-row fp16 A tile + single fp16 W buffer -> 48KB => 4 CTAs/SM @128thr
#define SM_A     0          // 16384 B (64 rows x 128 cols fp16, swizzled)
#define SM_W     16384      // 32768 B (128 x 128 fp16, swizzled)
#define SM_QKV_TOT 49152

// ---------------- helpers ------------------------------------------------------
__device__ __forceinline__ uint32_t smem_u32(const void* p) {
    uint32_t a;
    asm("{ .reg .u64 t; cvta.to.shared.u64 t, %1; cvt.u32.u64 %0, t; }" : "=r"(a) : "l"(p));
    return a;
}
__device__ __forceinline__ uint32_t sw_off(int row, int chunk) {
    return (uint32_t)(row * 256 + ((chunk ^ (row & 7)) << 4));
}
__device__ __forceinline__ void cp16(uint32_t saddr, const void* g) {
    asm volatile("cp.async.cg.shared.global [%0], [%1], 16;"
                 :: "r"(saddr), "l"(g) : "memory");
}
#define CP_COMMIT() asm volatile("cp.async.commit_group;" ::: "memory")
#define CP_WAIT0()  asm volatile("cp.async.wait_group 0;" ::: "memory")

__device__ __forceinline__ void ldsm4a(uint32_t* r, uint32_t base, int mrow0, int kchunk) {
    int lane = threadIdx.x & 31;
    uint32_t a = base + sw_off(mrow0 + (lane & 15), kchunk + (lane >> 4));
    asm volatile("ldmatrix.sync.aligned.m8n8.x4.shared.b16 {%0,%1,%2,%3}, [%4];"
        : "=r"(r[0]), "=r"(r[1]), "=r"(r[2]), "=r"(r[3]) : "r"(a));
}
__device__ __forceinline__ void ldsm4b(uint32_t* r, uint32_t base, int nrow0, int kchunk) {
    int lane = threadIdx.x & 31;
    uint32_t a = base + sw_off(nrow0 + ((lane >> 4) << 3) + (lane & 7),
                               kchunk + ((lane >> 3) & 1));
    asm volatile("ldmatrix.sync.aligned.m8n8.x4.shared.b16 {%0,%1,%2,%3}, [%4];"
        : "=r"(r[0]), "=r"(r[1]), "=r"(r[2]), "=r"(r[3]) : "r"(a));
}
__device__ __forceinline__ void mma16816h(float* c, const uint32_t* a, const uint32_t* b) {
    asm volatile("mma.sync.aligned.m16n8k16.row.col.f32.f16.f16.f32 "
        "{%0,%1,%2,%3}, {%4,%5,%6,%7}, {%8,%9}, {%0,%1,%2,%3};"
        : "+f"(c[0]), "+f"(c[1]), "+f"(c[2]), "+f"(c[3])
        : "r"(a[0]), "r"(a[1]), "r"(a[2]), "r"(a[3]), "r"(b[0]), "r"(b[1]));
}
__device__ __forceinline__ unsigned pack_h2(float x, float y) {
    __half2 p = __float22half2_rn(make_float2(x, y));
    return *(unsigned*)&p;
}
__device__ __forceinline__ float4 h4_to_f4(uint2 u) {
    __half2 a = *(__half2*)&u.x, b = *(__half2*)&u.y;
    float2 fa = __half22float2(a), fb = __half22float2(b);
    return make_float4(fa.x, fa.y, fb.x, fb.y);
}

// convert 64-row fp32 tile (from GLOBAL) -> fp16 A smem (128 threads)
__device__ __forceinline__ void x_to_smem64(const float* __restrict__ X, int row0, int N,
                                            char* sm) {
    for (int idx = threadIdx.x; idx < 1024; idx += 128) {
        int row = idx >> 4, c = idx & 15;
        int grow = row0 + row;
        uint4 hv = make_uint4(0, 0, 0, 0);
        if (grow < N) {
            float4 v0 = ((const float4*)X)[(size_t)grow * 32 + c * 2];
            float4 v1 = ((const float4*)X)[(size_t)grow * 32 + c * 2 + 1];
            hv.x = pack_h2(v0.x, v0.y); hv.y = pack_h2(v0.z, v0.w);
            hv.z = pack_h2(v1.x, v1.y); hv.w = pack_h2(v1.z, v1.w);
        }
        *(uint4*)(sm + SM_A + sw_off(row, c)) = hv;
    }
}

// async load of fp16 weight o into the single W smem buffer (128 threads)
__device__ __forceinline__ void w_to_smem_async(int o, uint32_t sb) {
    const char* wf = (const char*)&g_wf[o * DIMN * DIMN];
#pragma unroll
    for (int j = 0; j < 16; j++) {
        int idx = threadIdx.x + j * 128;
        int row = idx >> 4, c = idx & 15;
        cp16(sb + SM_W + sw_off(row, c), wf + idx * 16);
    }
}

// single-pass fp16 GEMM; warp tile 32(m) x 64(n); c_[2][8][4]
// per kk: 6 LDSM.x4 feed 16 MMAs
__device__ __forceinline__ void compute_tile(uint32_t sb, float c_[2][8][4],
                                             int wm, int wn) {
#pragma unroll
    for (int kk = 0; kk < 8; kk++) {
        uint32_t a[2][4], b[4][4];
        ldsm4a(a[0], sb + SM_A, wm * 32,      kk * 2);
        ldsm4a(a[1], sb + SM_A, wm * 32 + 16, kk * 2);
#pragma unroll
        for (int p = 0; p < 4; p++)
            ldsm4b(b[p], sb + SM_W, wn * 64 + p * 16, kk * 2);
#pragma unroll
        for (int mt = 0; mt < 2; mt++)
#pragma unroll
            for (int p = 0; p < 4; p++) {
                mma16816h(c_[mt][2 * p],     a[mt], &b[p][0]);
                mma16816h(c_[mt][2 * p + 1], a[mt], &b[p][2]);
            }
    }
}

// ---------------- P = Wp @ Wv + zero g_cnt --------------------------------------
__global__ void __launch_bounds__(128)
k_wpv(const float* __restrict__ Wp, const float* __restrict__ Wv, int N) {
    __shared__ float wp_row[DIMN];
    int gidx = blockIdx.x * 128 + threadIdx.x;
    for (int j = gidx; j < N; j += gridDim.x * 128) g_cnt[j] = 0;
    if (blockIdx.x < DIMN) {
        int i = blockIdx.x, j = threadIdx.x;
        wp_row[j] = Wp[i * DIMN + j];
        __syncthreads();
        float acc = 0.f;
#pragma unroll 8
        for (int k = 0; k < DIMN; k++)
            acc += wp_row[k] * Wv[k * DIMN + j];
        g_wpv[i * DIMN + j] = acc;
    }
}

// ---------------- weight fp16 convert (Wq, Wk, P) + dst histogram ---------------
__global__ void __launch_bounds__(256)
k_prephist(const float* __restrict__ Wq, const float* __restrict__ Wk,
           const int* __restrict__ edges, int E) {
    int i = blockIdx.x * 256 + threadIdx.x;
    if (i < 3 * DIMN * DIMN) {
        const float* srcs[3] = {Wq, Wk, g_wpv};
        g_wf[i] = __float2half(srcs[i >> 14][i & 16383]);
    }
    if (i < E) atomicAdd(&g_cnt[__ldg(&edges[E + i])], 1);
}

// ---------------- parallel scan: block-scan / top-scan / add-back ---------------
__global__ void __launch_bounds__(1024)
k_scanblk(int N) {
    __shared__ int sdata[1024];
    int t = threadIdx.x;
    int i = blockIdx.x * 1024 + t;
    int v = (i < N) ? g_cnt[i] : 0;
    sdata[t] = v;
    __syncthreads();
    for (int d = 1; d < 1024; d <<= 1) {
        int val = (t >= d) ? sdata[t - d] : 0;
        __syncthreads();
        sdata[t] += val;
        __syncthreads();
    }
    if (i < N) g_pos[i] = sdata[t] - v;
    if (t == 1023) g_blk[blockIdx.x] = sdata[1023];
}

__global__ void __launch_bounds__(128)
k_scantop(int nb) {
    __shared__ int sdata[128];
    int t = threadIdx.x;
    int v = (t < nb) ? g_blk[t] : 0;
    sdata[t] = v;
    __syncthreads();
    for (int d = 1; d < 128; d <<= 1) {
        int val = (t >= d) ? sdata[t - d] : 0;
        __syncthreads();
        sdata[t] += val;
        __syncthreads();
    }
    if (t < nb) g_blkoff[t] = sdata[t] - v;
}

__global__ void __launch_bounds__(1024)
k_addoff(int N) {
    int i = blockIdx.x * 1024 + threadIdx.x;
    if (i < N) g_pos[i] += g_blkoff[blockIdx.x];
}

__global__ void __launch_bounds__(256)
k_scatter(const int* __restrict__ edges, int E) {
    int e = blockIdx.x * 256 + threadIdx.x;
    if (e >= E) return;
    int s  = __ldg(&edges[e]);
    int dn = __ldg(&edges[E + e]);
    int p = atomicAdd(&g_pos[dn], 1);
    g_e2[p] = make_int2(s, dn);          // one 8B store instead of two 4B
}

// ---------------- fused Q/K/U GEMM, fp16 single-pass, 4 CTAs/SM -----------------
__global__ void __launch_bounds__(128, 4)
k_qkv(const float* __restrict__ h, int N) {
    extern __shared__ char sm[];
    uint32_t sb = smem_u32(sm);
    const int tid = threadIdx.x;
    const int row0 = blockIdx.x * 64;
    const int lane = tid & 31, w = tid >> 5, wm = w >> 1, wn = w & 1;
    const int gid = lane >> 2, tig = lane & 3;

    // W0 fetch first, overlapping state init + x convert
    w_to_smem_async(0, sb);
    CP_COMMIT();

    if (tid < 64 && row0 + tid < N) g_sum[row0 + tid] = 0.f;
    for (int idx = tid; idx < 64 * 32; idx += 128) {
        int r = idx >> 5;
        if (row0 + r < N)
            ((float4*)g_agg)[(size_t)(row0 + r) * 32 + (idx & 31)] = make_float4(0, 0, 0, 0);
    }

    x_to_smem64(h, row0, N, sm);

#pragma unroll
    for (int o = 0; o < 3; o++) {
        CP_WAIT0();
        __syncthreads();               // W(o) resident

        float c_[2][8][4];
#pragma unroll
        for (int mt = 0; mt < 2; mt++)
#pragma unroll
            for (int nt = 0; nt < 8; nt++)
#pragma unroll
                for (int j = 0; j < 4; j++) c_[mt][nt][j] = 0.f;

        compute_tile(sb, c_, wm, wn);

        __syncthreads();               // all warps done reading W(o)
        if (o < 2) {
            w_to_smem_async(o + 1, sb);    // next W overlaps epilogue
            CP_COMMIT();
        }

        __half* outp = (o == 0) ? g_q : ((o == 1) ? g_k : g_u);
#pragma unroll
        for (int mt = 0; mt < 2; mt++) {
            int r_lo = row0 + wm * 32 + mt * 16 + gid;
#pragma unroll
            for (int nt = 0; nt < 8; nt++) {
                int col = wn * 64 + nt * 8 + tig * 2;
                if (r_lo < N) {
                    __half2 p = __float22half2_rn(make_float2(c_[mt][nt][0], c_[mt][nt][1]));
                    *(__half2*)&outp[(size_t)r_lo * DIMN + col] = p;
                }
                if (r_lo + 8 < N) {
                    __half2 p = __float22half2_rn(make_float2(c_[mt][nt][2], c_[mt][nt][3]));
                    *(__half2*)&outp[(size_t)(r_lo + 8) * DIMN + col] = p;
                }
            }
        }
    }
}

// ---------------- edge phase on dst-sorted edges: 4 edges per warp --------------
// ex = exp(q[dst].k[src]/sqrt(d)); sum[dst] += ex; agg[dst] += ex*u[src].
__global__ void __launch_bounds__(256)
k_edge(int E) {
    int warp = blockIdx.x * 8 + (threadIdx.x >> 5);
    int e0 = warp * 4;
    if (e0 >= E) return;
    int lane = threadIdx.x & 31;

    int2 ei = make_int2(0, 0);
    if (lane < 4 && e0 + lane < E) ei = __ldg(&g_e2[e0 + lane]);

    int s[4], dn[4];
    int nok = min(4, E - e0);
#pragma unroll
    for (int j = 0; j < 4; j++) {
        s[j]  = __shfl_sync(0xffffffffu, ei.x, j);
        dn[j] = __shfl_sync(0xffffffffu, ei.y, j);
    }

    uint2 qr[4], kr[4], ur[4];
#pragma unroll
    for (int j = 0; j < 4; j++) {
        qr[j] = ((const uint2*)g_q)[(size_t)dn[j] * 32 + lane];
        kr[j] = ((const uint2*)g_k)[(size_t)s[j] * 32 + lane];
        ur[j] = ((const uint2*)g_u)[(size_t)s[j] * 32 + lane];
    }

    float ex[4];
    float4 uv[4];
#pragma unroll
    for (int j = 0; j < 4; j++) {
        float4 qv = h4_to_f4(qr[j]);
        float4 kv = h4_to_f4(kr[j]);
        uv[j] = h4_to_f4(ur[j]);
        float dot = qv.x * kv.x + qv.y * kv.y + qv.z * kv.z + qv.w * kv.w;
#pragma unroll
        for (int o = 16; o > 0; o >>= 1) dot += __shfl_xor_sync(0xffffffffu, dot, o);
        float sc = fminf(fmaxf(dot * 0.08838834764831845f, -60.f), 60.f);
        ex[j] = __expf(sc);
    }

    int cur = dn[0];
    float ss = 0.f;
    float4 acc = make_float4(0.f, 0.f, 0.f, 0.f);
#pragma unroll
    for (int j = 0; j < 4; j++) {
        if (j >= nok) break;
        if (dn[j] != cur) {
            float* dst = &g_agg[(size_t)cur * DIMN + lane * 4];
            asm volatile("red.relaxed.gpu.global.add.v4.f32 [%0], {%1, %2, %3, %4};"
                :: "l"(dst), "f"(acc.x), "f"(acc.y), "f"(acc.z), "f"(acc.w) : "memory");
            if (lane == 0)
                asm volatile("red.relaxed.gpu.global.add.f32 [%0], %1;"
                    :: "l"(&g_sum[cur]), "f"(ss) : "memory");
            cur = dn[j]; ss = 0.f; acc = make_float4(0.f, 0.f, 0.f, 0.f);
        }
        ss += ex[j];
        acc.x += ex[j] * uv[j].x; acc.y += ex[j] * uv[j].y;
        acc.z += ex[j] * uv[j].z; acc.w += ex[j] * uv[j].w;
    }
    float* dst = &g_agg[(size_t)cur * DIMN + lane * 4];
    asm volatile("red.relaxed.gpu.global.add.v4.f32 [%0], {%1, %2, %3, %4};"
        :: "l"(dst), "f"(acc.x), "f"(acc.y), "f"(acc.z), "f"(acc.w) : "memory");
    if (lane == 0)
        asm volatile("red.relaxed.gpu.global.add.f32 [%0], %1;"
            :: "l"(&g_sum[cur]), "f"(ss) : "memory");
}

// ---------------- epilogue: out = relu(agg/(sum+eps) + bp + h) -------------------
__global__ void __launch_bounds__(256)
k_norm(const float* __restrict__ h, const float* __restrict__ bp,
       float* __restrict__ out, int N) {
    int r = blockIdx.x * 8 + (threadIdx.x >> 5);
    if (r >= N) return;
    int lane = threadIdx.x & 31;

    float inv = 1.0f / (__ldg(&g_sum[r]) + 1e-9f);
    float4 a = ((const float4*)g_agg)[(size_t)r * 32 + lane];
    float4 hh = __ldg(&((const float4*)h)[(size_t)r * 32 + lane]);
    float4 b = __ldg(&((const float4*)bp)[lane]);
    float4 v;
    v.x = fmaxf(a.x * inv + b.x + hh.x, 0.f);
    v.y = fmaxf(a.y * inv + b.y + hh.y, 0.f);
    v.z = fmaxf(a.z * inv + b.z + hh.z, 0.f);
    v.w = fmaxf(a.w * inv + b.w + hh.w, 0.f);
    ((float4*)out)[(size_t)r * 32 + lane] = v;
}

// ---------------- launch -------------------------------------------------------
extern "C" void kernel_launch(void* const* d_in, const int* in_sizes, int n_in,
                              void* d_out, int out_size) {
    const float* h     = (const float*)d_in[0];
    const int*   edges = (const int*)d_in[1];
    const float* Wq    = (const float*)d_in[2];
    const float* Wk    = (const float*)d_in[3];
    const float* Wv    = (const float*)d_in[4];
    const float* Wp    = (const float*)d_in[5];
    const float* bp    = (const float*)d_in[6];
    float*       out   = (float*)d_out;

    int N   = in_sizes[0] / DIMN;
    int E   = in_sizes[1] / 2;
    int NB  = (N + 63) / 64;
    int NB2 = (N + 1023) / 1024;

    cudaFuncSetAttribute(k_qkv, cudaFuncAttributeMaxDynamicSharedMemorySize, SM_QKV_TOT);

    k_wpv<<<784, 128>>>(Wp, Wv, N);                          // 0
    k_prephist<<<(E + 255) / 256, 256>>>(Wq, Wk, edges, E);  // 1
    k_scanblk<<<NB2, 1024>>>(N);                             // 2
    k_qkv<<<NB, 128, SM_QKV_TOT>>>(h, N);                    // 3  <- ncu slot
    k_scantop<<<1, 128>>>(NB2);                              // 4
    k_addoff<<<NB2, 1024>>>(N);                              // 5
    k_scatter<<<(E + 255) / 256, 256>>>(edges, E);           // 6
    k_edge<<<(E + 31) / 32, 256>>>(E);                       // 7
    k_norm<<<(N + 7) / 8, 256>>>(h, bp, out, N);             // 8
}

// round 16
// speedup vs baseline: 1.0321x; 1.0321x over previous
#include <cuda_runtime.h>
#include <cuda_bf16.h>
#include <cuda_fp16.h>
#include <cstdint>

#define DIMN 128
#define NMAX 100000
#define EMAX 600000

// ---------------- scratch (device globals; no allocation allowed) -------------
__device__ __half   g_q[NMAX * DIMN];     // fp16 projections
__device__ __half   g_k[NMAX * DIMN];
__device__ __half   g_u[NMAX * DIMN];     // u = h @ (Wp@Wv)^T
__device__ float    g_agg[NMAX * DIMN];   // fp32 accumulator
__device__ float    g_sum[NMAX];
__device__ int      g_cnt[NMAX];
__device__ int      g_pos[NMAX];
__device__ int      g_blk[128];
__device__ int      g_blkoff[128];
__device__ int2     g_e2[EMAX];           // dst-sorted edges: (src, dst)
__device__ float    g_wpv[DIMN * DIMN];   // P = Wp @ Wv (fp32)
__device__ __half   g_wf[3 * DIMN * DIMN];  // fp16 Wq, Wk, P

// ---------------- smem layout (bytes, dynamic) ---------------------------------
// 64-row fp16 A tile + single fp16 W buffer -> 48KB => 3 CTAs/SM @256thr
#define SM_A     0          // 16384 B (64 rows x 128 cols fp16, swizzled)
#define SM_W     16384      // 32768 B (128 x 128 fp16, swizzled)
#define SM_QKV_TOT 49152

// ---------------- helpers ------------------------------------------------------
__device__ __forceinline__ uint32_t smem_u32(const void* p) {
    uint32_t a;
    asm("{ .reg .u64 t; cvta.to.shared.u64 t, %1; cvt.u32.u64 %0, t; }" : "=r"(a) : "l"(p));
    return a;
}
__device__ __forceinline__ uint32_t sw_off(int row, int chunk) {
    return (uint32_t)(row * 256 + ((chunk ^ (row & 7)) << 4));
}
__device__ __forceinline__ void cp16(uint32_t saddr, const void* g) {
    asm volatile("cp.async.cg.shared.global [%0], [%1], 16;"
                 :: "r"(saddr), "l"(g) : "memory");
}
#define CP_COMMIT() asm volatile("cp.async.commit_group;" ::: "memory")
#define CP_WAIT0()  asm volatile("cp.async.wait_group 0;" ::: "memory")

__device__ __forceinline__ void ldsm4a(uint32_t* r, uint32_t base, int mrow0, int kchunk) {
    int lane = threadIdx.x & 31;
    uint32_t a = base + sw_off(mrow0 + (lane & 15), kchunk + (lane >> 4));
    asm volatile("ldmatrix.sync.aligned.m8n8.x4.shared.b16 {%0,%1,%2,%3}, [%4];"
        : "=r"(r[0]), "=r"(r[1]), "=r"(r[2]), "=r"(r[3]) : "r"(a));
}
__device__ __forceinline__ void ldsm4b(uint32_t* r, uint32_t base, int nrow0, int kchunk) {
    int lane = threadIdx.x & 31;
    uint32_t a = base + sw_off(nrow0 + ((lane >> 4) << 3) + (lane & 7),
                               kchunk + ((lane >> 3) & 1));
    asm volatile("ldmatrix.sync.aligned.m8n8.x4.shared.b16 {%0,%1,%2,%3}, [%4];"
        : "=r"(r[0]), "=r"(r[1]), "=r"(r[2]), "=r"(r[3]) : "r"(a));
}
__device__ __forceinline__ void mma16816h(float* c, const uint32_t* a, const uint32_t* b) {
    asm volatile("mma.sync.aligned.m16n8k16.row.col.f32.f16.f16.f32 "
        "{%0,%1,%2,%3}, {%4,%5,%6,%7}, {%8,%9}, {%0,%1,%2,%3};"
        : "+f"(c[0]), "+f"(c[1]), "+f"(c[2]), "+f"(c[3])
        : "r"(a[0]), "r"(a[1]), "r"(a[2]), "r"(a[3]), "r"(b[0]), "r"(b[1]));
}
__device__ __forceinline__ unsigned pack_h2(float x, float y) {
    __half2 p = __float22half2_rn(make_float2(x, y));
    return *(unsigned*)&p;
}
__device__ __forceinline__ float4 h4_to_f4(uint2 u) {
    __half2 a = *(__half2*)&u.x, b = *(__half2*)&u.y;
    float2 fa = __half22float2(a), fb = __half22float2(b);
    return make_float4(fa.x, fa.y, fb.x, fb.y);
}

// convert 64-row fp32 tile (from GLOBAL) -> fp16 A smem (256 threads)
__device__ __forceinline__ void x_to_smem64(const float* __restrict__ X, int row0, int N,
                                            char* sm) {
    for (int idx = threadIdx.x; idx < 1024; idx += 256) {
        int row = idx >> 4, c = idx & 15;
        int grow = row0 + row;
        uint4 hv = make_uint4(0, 0, 0, 0);
        if (grow < N) {
            float4 v0 = ((const float4*)X)[(size_t)grow * 32 + c * 2];
            float4 v1 = ((const float4*)X)[(size_t)grow * 32 + c * 2 + 1];
            hv.x = pack_h2(v0.x, v0.y); hv.y = pack_h2(v0.z, v0.w);
            hv.z = pack_h2(v1.x, v1.y); hv.w = pack_h2(v1.z, v1.w);
        }
        *(uint4*)(sm + SM_A + sw_off(row, c)) = hv;
    }
}

// async load of fp16 weight o into the single W smem buffer (256 threads)
__device__ __forceinline__ void w_to_smem_async(int o, uint32_t sb) {
    const char* wf = (const char*)&g_wf[o * DIMN * DIMN];
#pragma unroll
    for (int j = 0; j < 8; j++) {
        int idx = threadIdx.x + j * 256;
        int row = idx >> 4, c = idx & 15;
        cp16(sb + SM_W + sw_off(row, c), wf + idx * 16);
    }
}

// single-pass fp16 GEMM; warp tile 32(m) x 32(n); c_[2][4][4]  (R14-proven)
__device__ __forceinline__ void compute_tile32(uint32_t sb, float c_[2][4][4],
                                               int wm, int wn) {
#pragma unroll
    for (int kk = 0; kk < 8; kk++) {
        uint32_t a[2][4], b[2][4];
        ldsm4a(a[0], sb + SM_A, wm * 32,      kk * 2);
        ldsm4a(a[1], sb + SM_A, wm * 32 + 16, kk * 2);
        ldsm4b(b[0], sb + SM_W, wn * 32,      kk * 2);
        ldsm4b(b[1], sb + SM_W, wn * 32 + 16, kk * 2);
#pragma unroll
        for (int mt = 0; mt < 2; mt++)
#pragma unroll
            for (int p = 0; p < 2; p++) {
                mma16816h(c_[mt][2 * p],     a[mt], &b[p][0]);
                mma16816h(c_[mt][2 * p + 1], a[mt], &b[p][2]);
            }
    }
}

// ---------------- P = Wp @ Wv + zero g_cnt --------------------------------------
__global__ void __launch_bounds__(128)
k_wpv(const float* __restrict__ Wp, const float* __restrict__ Wv, int N) {
    __shared__ float wp_row[DIMN];
    int gidx = blockIdx.x * 128 + threadIdx.x;
    for (int j = gidx; j < N; j += gridDim.x * 128) g_cnt[j] = 0;
    if (blockIdx.x < DIMN) {
        int i = blockIdx.x, j = threadIdx.x;
        wp_row[j] = Wp[i * DIMN + j];
        __syncthreads();
        float acc = 0.f;
#pragma unroll 8
        for (int k = 0; k < DIMN; k++)
            acc += wp_row[k] * Wv[k * DIMN + j];
        g_wpv[i * DIMN + j] = acc;
    }
}

// ---------------- weight fp16 convert (Wq, Wk, P) + dst histogram ---------------
__global__ void __launch_bounds__(256)
k_prephist(const float* __restrict__ Wq, const float* __restrict__ Wk,
           const int* __restrict__ edges, int E) {
    int i = blockIdx.x * 256 + threadIdx.x;
    if (i < 3 * DIMN * DIMN) {
        const float* srcs[3] = {Wq, Wk, g_wpv};
        g_wf[i] = __float2half(srcs[i >> 14][i & 16383]);
    }
    if (i < E) atomicAdd(&g_cnt[__ldg(&edges[E + i])], 1);
}

// ---------------- parallel scan: block-scan / top-scan / add-back ---------------
__global__ void __launch_bounds__(1024)
k_scanblk(int N) {
    __shared__ int sdata[1024];
    int t = threadIdx.x;
    int i = blockIdx.x * 1024 + t;
    int v = (i < N) ? g_cnt[i] : 0;
    sdata[t] = v;
    __syncthreads();
    for (int d = 1; d < 1024; d <<= 1) {
        int val = (t >= d) ? sdata[t - d] : 0;
        __syncthreads();
        sdata[t] += val;
        __syncthreads();
    }
    if (i < N) g_pos[i] = sdata[t] - v;
    if (t == 1023) g_blk[blockIdx.x] = sdata[1023];
}

__global__ void __launch_bounds__(128)
k_scantop(int nb) {
    __shared__ int sdata[128];
    int t = threadIdx.x;
    int v = (t < nb) ? g_blk[t] : 0;
    sdata[t] = v;
    __syncthreads();
    for (int d = 1; d < 128; d <<= 1) {
        int val = (t >= d) ? sdata[t - d] : 0;
        __syncthreads();
        sdata[t] += val;
        __syncthreads();
    }
    if (t < nb) g_blkoff[t] = sdata[t] - v;
}

__global__ void __launch_bounds__(1024)
k_addoff(int N) {
    int i = blockIdx.x * 1024 + threadIdx.x;
    if (i < N) g_pos[i] += g_blkoff[blockIdx.x];
}

__global__ void __launch_bounds__(256)
k_scatter(const int* __restrict__ edges, int E) {
    int e = blockIdx.x * 256 + threadIdx.x;
    if (e >= E) return;
    int s  = __ldg(&edges[e]);
    int dn = __ldg(&edges[E + e]);
    int p = atomicAdd(&g_pos[dn], 1);
    g_e2[p] = make_int2(s, dn);          // one 8B store
}

// ---------------- fused Q/K/U GEMM, fp16 single-pass, 3 CTAs/SM (R14 config) ----
__global__ void __launch_bounds__(256, 3)
k_qkv(const float* __restrict__ h, int N) {
    extern __shared__ char sm[];
    uint32_t sb = smem_u32(sm);
    const int tid = threadIdx.x;
    const int row0 = blockIdx.x * 64;
    const int lane = tid & 31, w = tid >> 5, wm = w >> 2, wn = w & 3;
    const int gid = lane >> 2, tig = lane & 3;

    // W0 fetch first, overlapping state init + x convert
    w_to_smem_async(0, sb);
    CP_COMMIT();

    if (tid < 64 && row0 + tid < N) g_sum[row0 + tid] = 0.f;
    for (int idx = tid; idx < 64 * 32; idx += 256) {
        int r = idx >> 5;
        if (row0 + r < N)
            ((float4*)g_agg)[(size_t)(row0 + r) * 32 + (idx & 31)] = make_float4(0, 0, 0, 0);
    }

    x_to_smem64(h, row0, N, sm);

#pragma unroll
    for (int o = 0; o < 3; o++) {
        CP_WAIT0();
        __syncthreads();               // W(o) resident

        float c_[2][4][4];
#pragma unroll
        for (int mt = 0; mt < 2; mt++)
#pragma unroll
            for (int nt = 0; nt < 4; nt++)
#pragma unroll
                for (int j = 0; j < 4; j++) c_[mt][nt][j] = 0.f;

        compute_tile32(sb, c_, wm, wn);

        __syncthreads();               // all warps done reading W(o)
        if (o < 2) {
            w_to_smem_async(o + 1, sb);    // next W overlaps epilogue
            CP_COMMIT();
        }

        __half* outp = (o == 0) ? g_q : ((o == 1) ? g_k : g_u);
#pragma unroll
        for (int mt = 0; mt < 2; mt++) {
            int r_lo = row0 + wm * 32 + mt * 16 + gid;
#pragma unroll
            for (int nt = 0; nt < 4; nt++) {
                int col = wn * 32 + nt * 8 + tig * 2;
                if (r_lo < N) {
                    __half2 p = __float22half2_rn(make_float2(c_[mt][nt][0], c_[mt][nt][1]));
                    *(__half2*)&outp[(size_t)r_lo * DIMN + col] = p;
                }
                if (r_lo + 8 < N) {
                    __half2 p = __float22half2_rn(make_float2(c_[mt][nt][2], c_[mt][nt][3]));
                    *(__half2*)&outp[(size_t)(r_lo + 8) * DIMN + col] = p;
                }
            }
        }
    }
}

// ---------------- edge phase on dst-sorted edges: 4 edges per warp --------------
// ex = exp(q[dst].k[src]/sqrt(d)); sum[dst] += ex; agg[dst] += ex*u[src].
__global__ void __launch_bounds__(256)
k_edge(int E) {
    int warp = blockIdx.x * 8 + (threadIdx.x >> 5);
    int e0 = warp * 4;
    if (e0 >= E) return;
    int lane = threadIdx.x & 31;

    int2 ei = make_int2(0, 0);
    if (lane < 4 && e0 + lane < E) ei = __ldg(&g_e2[e0 + lane]);

    int s[4], dn[4];
    int nok = min(4, E - e0);
#pragma unroll
    for (int j = 0; j < 4; j++) {
        s[j]  = __shfl_sync(0xffffffffu, ei.x, j);
        dn[j] = __shfl_sync(0xffffffffu, ei.y, j);
    }

    uint2 qr[4], kr[4], ur[4];
#pragma unroll
    for (int j = 0; j < 4; j++) {
        qr[j] = ((const uint2*)g_q)[(size_t)dn[j] * 32 + lane];
        kr[j] = ((const uint2*)g_k)[(size_t)s[j] * 32 + lane];
        ur[j] = ((const uint2*)g_u)[(size_t)s[j] * 32 + lane];
    }

    float ex[4];
    float4 uv[4];
#pragma unroll
    for (int j = 0; j < 4; j++) {
        float4 qv = h4_to_f4(qr[j]);
        float4 kv = h4_to_f4(kr[j]);
        uv[j] = h4_to_f4(ur[j]);
        float dot = qv.x * kv.x + qv.y * kv.y + qv.z * kv.z + qv.w * kv.w;
#pragma unroll
        for (int o = 16; o > 0; o >>= 1) dot += __shfl_xor_sync(0xffffffffu, dot, o);
        float sc = fminf(fmaxf(dot * 0.08838834764831845f, -60.f), 60.f);
        ex[j] = __expf(sc);
    }

    int cur = dn[0];
    float ss = 0.f;
    float4 acc = make_float4(0.f, 0.f, 0.f, 0.f);
#pragma unroll
    for (int j = 0; j < 4; j++) {
        if (j >= nok) break;
        if (dn[j] != cur) {
            float* dst = &g_agg[(size_t)cur * DIMN + lane * 4];
            asm volatile("red.relaxed.gpu.global.add.v4.f32 [%0], {%1, %2, %3, %4};"
                :: "l"(dst), "f"(acc.x), "f"(acc.y), "f"(acc.z), "f"(acc.w) : "memory");
            if (lane == 0)
                asm volatile("red.relaxed.gpu.global.add.f32 [%0], %1;"
                    :: "l"(&g_sum[cur]), "f"(ss) : "memory");
            cur = dn[j]; ss = 0.f; acc = make_float4(0.f, 0.f, 0.f, 0.f);
        }
        ss += ex[j];
        acc.x += ex[j] * uv[j].x; acc.y += ex[j] * uv[j].y;
        acc.z += ex[j] * uv[j].z; acc.w += ex[j] * uv[j].w;
    }
    float* dst = &g_agg[(size_t)cur * DIMN + lane * 4];
    asm volatile("red.relaxed.gpu.global.add.v4.f32 [%0], {%1, %2, %3, %4};"
        :: "l"(dst), "f"(acc.x), "f"(acc.y), "f"(acc.z), "f"(acc.w) : "memory");
    if (lane == 0)
        asm volatile("red.relaxed.gpu.global.add.f32 [%0], %1;"
            :: "l"(&g_sum[cur]), "f"(ss) : "memory");
}

// ---------------- epilogue: out = relu(agg/(sum+eps) + bp + h) -------------------
__global__ void __launch_bounds__(256)
k_norm(const float* __restrict__ h, const float* __restrict__ bp,
       float* __restrict__ out, int N) {
    int r = blockIdx.x * 8 + (threadIdx.x >> 5);
    if (r >= N) return;
    int lane = threadIdx.x & 31;

    float inv = 1.0f / (__ldg(&g_sum[r]) + 1e-9f);
    float4 a = ((const float4*)g_agg)[(size_t)r * 32 + lane];
    float4 hh = __ldg(&((const float4*)h)[(size_t)r * 32 + lane]);
    float4 b = __ldg(&((const float4*)bp)[lane]);
    float4 v;
    v.x = fmaxf(a.x * inv + b.x + hh.x, 0.f);
    v.y = fmaxf(a.y * inv + b.y + hh.y, 0.f);
    v.z = fmaxf(a.z * inv + b.z + hh.z, 0.f);
    v.w = fmaxf(a.w * inv + b.w + hh.w, 0.f);
    ((float4*)out)[(size_t)r * 32 + lane] = v;
}

// ---------------- launch -------------------------------------------------------
extern "C" void kernel_launch(void* const* d_in, const int* in_sizes, int n_in,
                              void* d_out, int out_size) {
    const float* h     = (const float*)d_in[0];
    const int*   edges = (const int*)d_in[1];
    const float* Wq    = (const float*)d_in[2];
    const float* Wk    = (const float*)d_in[3];
    const float* Wv    = (const float*)d_in[4];
    const float* Wp    = (const float*)d_in[5];
    const float* bp    = (const float*)d_in[6];
    float*       out   = (float*)d_out;

    int N   = in_sizes[0] / DIMN;
    int E   = in_sizes[1] / 2;
    int NB  = (N + 63) / 64;
    int NB2 = (N + 1023) / 1024;

    cudaFuncSetAttribute(k_qkv, cudaFuncAttributeMaxDynamicSharedMemorySize, SM_QKV_TOT);

    k_wpv<<<784, 128>>>(Wp, Wv, N);                          // 0
    k_prephist<<<(E + 255) / 256, 256>>>(Wq, Wk, edges, E);  // 1
    k_scanblk<<<NB2, 1024>>>(N);                             // 2
    k_qkv<<<NB, 256, SM_QKV_TOT>>>(h, N);                    // 3  <- ncu slot
    k_scantop<<<1, 128>>>(NB2);                              // 4
    k_addoff<<<NB2, 1024>>>(N);                              // 5
    k_scatter<<<(E + 255) / 256, 256>>>(edges, E);           // 6
    k_edge<<<(E + 31) / 32, 256>>>(E);                       // 7
    k_norm<<<(N + 7) / 8, 256>>>(h, bp, out, N);             // 8
}